// round 3
// baseline (speedup 1.0000x reference)
#include <cuda_runtime.h>
#include <math_constants.h>

static constexpr int NPTS  = 4096;
static constexpr int NUP   = 16384;
static constexpr int BATCH = 4;
static constexpr int C     = 64;
static constexpr int TPB   = 64;    // threads per block
static constexpr int Q     = 4;     // queries per thread

static constexpr int SMEM_BYTES = NPTS * 16;   // pos tile only (float4/point)

__constant__ __align__(16) float cW[C * C];
__constant__ __align__(16) float cB[C];

// ---- packed f32x2 helpers (Blackwell) ----
__device__ __forceinline__ unsigned long long pk2(float lo, float hi) {
    unsigned long long r;
    asm("mov.b64 %0, {%1, %2};" : "=l"(r) : "f"(lo), "f"(hi));
    return r;
}
__device__ __forceinline__ unsigned long long fma2(unsigned long long a,
                                                   unsigned long long b,
                                                   unsigned long long c) {
    unsigned long long d;
    asm("fma.rn.f32x2 %0, %1, %2, %3;" : "=l"(d) : "l"(a), "l"(b), "l"(c));
    return d;
}
__device__ __forceinline__ void unpk2(unsigned long long v, float& lo, float& hi) {
    asm("mov.b64 {%0, %1}, %2;" : "=f"(lo), "=f"(hi) : "l"(v));
}

__global__ void __launch_bounds__(TPB, 3)
up_kernel(const float* __restrict__ feature,
          const float* __restrict__ pos,
          const float* __restrict__ pos_up,
          float* __restrict__ out)
{
    extern __shared__ float4 spos[];   // [NPTS]: x,y,z, 0.5*|p|^2

    const int b   = blockIdx.y;
    const int tid = threadIdx.x;

    // ---- stage pos tile ----
    {
        const float* pb = pos + (size_t)b * NPTS * 3;
        for (int j = tid; j < NPTS; j += TPB) {
            float x = pb[3 * j + 0];
            float y = pb[3 * j + 1];
            float z = pb[3 * j + 2];
            spos[j] = make_float4(x, y, z, 0.5f * (x * x + y * y + z * z));
        }
    }
    __syncthreads();

    // ---- per-thread: 4 queries, strided by TPB for coalescing ----
    const int qbase = blockIdx.x * (TPB * Q) + tid;

    float pux[Q], puy[Q], puz[Q], nu[Q];
    #pragma unroll
    for (int k = 0; k < Q; ++k) {
        const int q = qbase + k * TPB;
        const float* pu = pos_up + (size_t)(b * NUP + q) * 3;
        pux[k] = pu[0]; puy[k] = pu[1]; puz[k] = pu[2];
        nu[k]  = pux[k] * pux[k] + puy[k] * puy[k] + puz[k] * puz[k];
    }

    const unsigned long long nxAB = pk2(-pux[0], -pux[1]);
    const unsigned long long nyAB = pk2(-puy[0], -puy[1]);
    const unsigned long long nzAB = pk2(-puz[0], -puz[1]);
    const unsigned long long nxCD = pk2(-pux[2], -pux[3]);
    const unsigned long long nyCD = pk2(-puy[2], -puy[3]);
    const unsigned long long nzCD = pk2(-puz[2], -puz[3]);

    // top-3 state per query (s = 0.5|p|^2 - pu.p, monotone in d^2)
    float v0[Q], v1[Q], v2[Q];
    int   i0[Q], i1[Q], i2[Q];
    #pragma unroll
    for (int k = 0; k < Q; ++k) {
        v0[k] = v1[k] = v2[k] = CUDART_INF_F;
        i0[k] = i1[k] = i2[k] = 0;
    }
    float vmax = CUDART_INF_F;   // max over v2[k]; gate for fast path

    #pragma unroll 4
    for (int j = 0; j < NPTS; ++j) {
        float4 p = spos[j];
        unsigned long long px = pk2(p.x, p.x);
        unsigned long long py = pk2(p.y, p.y);
        unsigned long long pz = pk2(p.z, p.z);
        unsigned long long ph = pk2(p.w, p.w);

        unsigned long long sAB = fma2(px, nxAB, ph);
        sAB = fma2(py, nyAB, sAB);
        sAB = fma2(pz, nzAB, sAB);
        unsigned long long sCD = fma2(px, nxCD, ph);
        sCD = fma2(py, nyCD, sCD);
        sCD = fma2(pz, nzCD, sCD);

        float s[Q];
        unpk2(sAB, s[0], s[1]);
        unpk2(sCD, s[2], s[3]);

        float smin = fminf(fminf(s[0], s[1]), fminf(s[2], s[3]));
        if (smin < vmax) {               // slow path, divergent but short
            #pragma unroll
            for (int k = 0; k < Q; ++k) {
                float sk = s[k];
                if (sk < v2[k]) {
                    if (sk < v1[k]) {
                        v2[k] = v1[k]; i2[k] = i1[k];
                        if (sk < v0[k]) { v1[k] = v0[k]; i1[k] = i0[k]; v0[k] = sk; i0[k] = j; }
                        else            { v1[k] = sk;    i1[k] = j; }
                    } else { v2[k] = sk; i2[k] = j; }
                }
            }
            vmax = fmaxf(fmaxf(v2[0], v2[1]), fmaxf(v2[2], v2[3]));
        }
    }

    // ---- epilogue: one query at a time (keeps acc[] footprint small) ----
    const float4* cW4 = reinterpret_cast<const float4*>(cW);
    const float4* cB4 = reinterpret_cast<const float4*>(cB);

    #pragma unroll 1
    for (int k = 0; k < Q; ++k) {
        const int q = qbase + k * TPB;

        float w0 = 1.0f / (__fmaf_rn(2.0f, v0[k], nu[k]) + 1e-6f);
        float w1 = 1.0f / (__fmaf_rn(2.0f, v1[k], nu[k]) + 1e-6f);
        float w2 = 1.0f / (__fmaf_rn(2.0f, v2[k], nu[k]) + 1e-6f);
        float inv = 1.0f / (w0 + w1 + w2);
        w0 *= inv; w1 *= inv; w2 *= inv;

        const float4* f0 = reinterpret_cast<const float4*>(feature + (size_t)(b * NPTS + i0[k]) * C);
        const float4* f1 = reinterpret_cast<const float4*>(feature + (size_t)(b * NPTS + i1[k]) * C);
        const float4* f2 = reinterpret_cast<const float4*>(feature + (size_t)(b * NPTS + i2[k]) * C);

        float acc[64];
        #pragma unroll
        for (int m = 0; m < 16; ++m) {
            float4 bb = cB4[m];
            acc[4 * m + 0] = bb.x; acc[4 * m + 1] = bb.y;
            acc[4 * m + 2] = bb.z; acc[4 * m + 3] = bb.w;
        }

        for (int c4 = 0; c4 < 16; ++c4) {
            float4 a = __ldg(f0 + c4);
            float4 e = __ldg(f1 + c4);
            float4 g = __ldg(f2 + c4);
            float nf[4];
            nf[0] = __fmaf_rn(w0, a.x, __fmaf_rn(w1, e.x, w2 * g.x));
            nf[1] = __fmaf_rn(w0, a.y, __fmaf_rn(w1, e.y, w2 * g.y));
            nf[2] = __fmaf_rn(w0, a.z, __fmaf_rn(w1, e.z, w2 * g.z));
            nf[3] = __fmaf_rn(w0, a.w, __fmaf_rn(w1, e.w, w2 * g.w));

            const float4* wr = cW4 + (size_t)c4 * 4 * 16;   // rows 4*c4..4*c4+3, 16 float4 each
            #pragma unroll
            for (int kk = 0; kk < 4; ++kk) {
                float nfc = nf[kk];
                #pragma unroll
                for (int m = 0; m < 16; ++m) {
                    float4 wv = wr[kk * 16 + m];
                    acc[4 * m + 0] = __fmaf_rn(nfc, wv.x, acc[4 * m + 0]);
                    acc[4 * m + 1] = __fmaf_rn(nfc, wv.y, acc[4 * m + 1]);
                    acc[4 * m + 2] = __fmaf_rn(nfc, wv.z, acc[4 * m + 2]);
                    acc[4 * m + 3] = __fmaf_rn(nfc, wv.w, acc[4 * m + 3]);
                }
            }
        }

        float4* o4 = reinterpret_cast<float4*>(out + (size_t)(b * NUP + q) * C);
        #pragma unroll
        for (int m = 0; m < 16; ++m) {
            float4 v;
            v.x = fmaxf(acc[4 * m + 0], 0.0f);
            v.y = fmaxf(acc[4 * m + 1], 0.0f);
            v.z = fmaxf(acc[4 * m + 2], 0.0f);
            v.w = fmaxf(acc[4 * m + 3], 0.0f);
            o4[m] = v;
        }
    }
}

extern "C" void kernel_launch(void* const* d_in, const int* in_sizes, int n_in,
                              void* d_out, int out_size)
{
    const float* feature = (const float*)d_in[0];
    const float* pos     = (const float*)d_in[1];
    const float* pos_up  = (const float*)d_in[2];
    const float* W       = (const float*)d_in[3];
    const float* bias    = (const float*)d_in[4];
    float* out = (float*)d_out;

    // W, b -> constant bank (device-to-device async copies; graph-capturable)
    cudaMemcpyToSymbolAsync(cW, W,    C * C * sizeof(float), 0, cudaMemcpyDeviceToDevice, 0);
    cudaMemcpyToSymbolAsync(cB, bias, C * sizeof(float),     0, cudaMemcpyDeviceToDevice, 0);

    cudaFuncSetAttribute(up_kernel, cudaFuncAttributeMaxDynamicSharedMemorySize, SMEM_BYTES);

    dim3 grid(NUP / (TPB * Q), BATCH);
    up_kernel<<<grid, TPB, SMEM_BYTES>>>(feature, pos, pos_up, out);
}

// round 4
// speedup vs baseline: 3.0855x; 3.0855x over previous
#include <cuda_runtime.h>
#include <math_constants.h>

static constexpr int NPTS  = 4096;
static constexpr int NUP   = 16384;
static constexpr int BATCH = 4;
static constexpr int C     = 64;

static constexpr int S       = 4;              // point slices
static constexpr int SLICE   = NPTS / S;       // 1024 points per slice
static constexpr int TPB_A   = 128;
static constexpr int Q       = 4;              // queries per thread (phase A)
static constexpr int QTILE   = TPB_A * Q;      // 512 queries per block
static constexpr int TPB_B   = 256;

static constexpr int SMEM_A  = SLICE * 16;     // 16KB slice tile

__constant__ __align__(16) float cW[C * C];
__constant__ __align__(16) float cB[C];

// per-(slice, batch, query) top-3: values and indices (bitcast)
__device__ float4 g_scrV[S * BATCH * NUP];
__device__ float4 g_scrI[S * BATCH * NUP];

// ---- packed f32x2 helpers (Blackwell) ----
__device__ __forceinline__ unsigned long long pk2(float lo, float hi) {
    unsigned long long r;
    asm("mov.b64 %0, {%1, %2};" : "=l"(r) : "f"(lo), "f"(hi));
    return r;
}
__device__ __forceinline__ unsigned long long fma2(unsigned long long a,
                                                   unsigned long long b,
                                                   unsigned long long c) {
    unsigned long long d;
    asm("fma.rn.f32x2 %0, %1, %2, %3;" : "=l"(d) : "l"(a), "l"(b), "l"(c));
    return d;
}
__device__ __forceinline__ void unpk2(unsigned long long v, float& lo, float& hi) {
    asm("mov.b64 {%0, %1}, %2;" : "=f"(lo), "=f"(hi) : "l"(v));
}

// strict-< insert keeps earliest index on ties (jax.lax.top_k stability)
__device__ __forceinline__ void ins3(float v, int i,
                                     float& v0, float& v1, float& v2,
                                     int& i0, int& i1, int& i2) {
    if (v < v2) {
        if (v < v1) {
            v2 = v1; i2 = i1;
            if (v < v0) { v1 = v0; i1 = i0; v0 = v; i0 = i; }
            else        { v1 = v;  i1 = i; }
        } else { v2 = v; i2 = i; }
    }
}

// ================= Phase A: per-slice top-3 scan =================
__global__ void __launch_bounds__(TPB_A, 6)
knn_slice_kernel(const float* __restrict__ pos,
                 const float* __restrict__ pos_up)
{
    extern __shared__ float4 spos[];   // [SLICE]: x,y,z, 0.5*|p|^2

    const int s   = blockIdx.y;        // slice
    const int b   = blockIdx.z;        // batch
    const int tid = threadIdx.x;

    // stage slice tile
    {
        const float* pb = pos + ((size_t)b * NPTS + (size_t)s * SLICE) * 3;
        for (int j = tid; j < SLICE; j += TPB_A) {
            float x = pb[3 * j + 0];
            float y = pb[3 * j + 1];
            float z = pb[3 * j + 2];
            spos[j] = make_float4(x, y, z, 0.5f * (x * x + y * y + z * z));
        }
    }
    __syncthreads();

    const int qbase = blockIdx.x * QTILE + tid;

    float pux[Q], puy[Q], puz[Q];
    #pragma unroll
    for (int k = 0; k < Q; ++k) {
        const int q = qbase + k * TPB_A;
        const float* pu = pos_up + (size_t)(b * NUP + q) * 3;
        pux[k] = pu[0]; puy[k] = pu[1]; puz[k] = pu[2];
    }
    const unsigned long long nxAB = pk2(-pux[0], -pux[1]);
    const unsigned long long nyAB = pk2(-puy[0], -puy[1]);
    const unsigned long long nzAB = pk2(-puz[0], -puz[1]);
    const unsigned long long nxCD = pk2(-pux[2], -pux[3]);
    const unsigned long long nyCD = pk2(-puy[2], -puy[3]);
    const unsigned long long nzCD = pk2(-puz[2], -puz[3]);

    float v0[Q], v1[Q], v2[Q];
    int   i0[Q], i1[Q], i2[Q];
    #pragma unroll
    for (int k = 0; k < Q; ++k) {
        v0[k] = v1[k] = v2[k] = CUDART_INF_F;
        i0[k] = i1[k] = i2[k] = 0;
    }
    float vmax = CUDART_INF_F;

    const int jbase = s * SLICE;   // global point index offset

    #pragma unroll 4
    for (int j = 0; j < SLICE; ++j) {
        float4 p = spos[j];
        unsigned long long px = pk2(p.x, p.x);
        unsigned long long py = pk2(p.y, p.y);
        unsigned long long pz = pk2(p.z, p.z);
        unsigned long long ph = pk2(p.w, p.w);

        unsigned long long sAB = fma2(px, nxAB, ph);
        sAB = fma2(py, nyAB, sAB);
        sAB = fma2(pz, nzAB, sAB);
        unsigned long long sCD = fma2(px, nxCD, ph);
        sCD = fma2(py, nyCD, sCD);
        sCD = fma2(pz, nzCD, sCD);

        float sv[Q];
        unpk2(sAB, sv[0], sv[1]);
        unpk2(sCD, sv[2], sv[3]);

        float smin = fminf(fminf(sv[0], sv[1]), fminf(sv[2], sv[3]));
        if (smin < vmax) {
            #pragma unroll
            for (int k = 0; k < Q; ++k)
                ins3(sv[k], jbase + j, v0[k], v1[k], v2[k], i0[k], i1[k], i2[k]);
            vmax = fmaxf(fmaxf(v2[0], v2[1]), fmaxf(v2[2], v2[3]));
        }
    }

    #pragma unroll
    for (int k = 0; k < Q; ++k) {
        const int q = qbase + k * TPB_A;
        const size_t o = ((size_t)s * BATCH + b) * NUP + q;
        g_scrV[o] = make_float4(v0[k], v1[k], v2[k], 0.0f);
        g_scrI[o] = make_float4(__int_as_float(i0[k]), __int_as_float(i1[k]),
                                __int_as_float(i2[k]), 0.0f);
    }
}

// ================= Phase B: merge + interp + GEMM =================
__global__ void __launch_bounds__(TPB_B, 2)
epilogue_kernel(const float* __restrict__ feature,
                const float* __restrict__ pos_up,
                float* __restrict__ out)
{
    const int b = blockIdx.y;
    const int q = blockIdx.x * TPB_B + threadIdx.x;

    // merge S slice-top-3s (slice order == ascending index blocks; strict <)
    float v0 = CUDART_INF_F, v1 = CUDART_INF_F, v2 = CUDART_INF_F;
    int   i0 = 0, i1 = 0, i2 = 0;
    #pragma unroll
    for (int s = 0; s < S; ++s) {
        const size_t o = ((size_t)s * BATCH + b) * NUP + q;
        float4 vv = g_scrV[o];
        float4 ii = g_scrI[o];
        ins3(vv.x, __float_as_int(ii.x), v0, v1, v2, i0, i1, i2);
        ins3(vv.y, __float_as_int(ii.y), v0, v1, v2, i0, i1, i2);
        ins3(vv.z, __float_as_int(ii.z), v0, v1, v2, i0, i1, i2);
    }

    const float* pu = pos_up + (size_t)(b * NUP + q) * 3;
    const float pux = pu[0], puy = pu[1], puz = pu[2];
    const float nu  = pux * pux + puy * puy + puz * puz;

    float w0 = 1.0f / (__fmaf_rn(2.0f, v0, nu) + 1e-6f);
    float w1 = 1.0f / (__fmaf_rn(2.0f, v1, nu) + 1e-6f);
    float w2 = 1.0f / (__fmaf_rn(2.0f, v2, nu) + 1e-6f);
    float inv = 1.0f / (w0 + w1 + w2);
    w0 *= inv; w1 *= inv; w2 *= inv;

    const float4* f0 = reinterpret_cast<const float4*>(feature + (size_t)(b * NPTS + i0) * C);
    const float4* f1 = reinterpret_cast<const float4*>(feature + (size_t)(b * NPTS + i1) * C);
    const float4* f2 = reinterpret_cast<const float4*>(feature + (size_t)(b * NPTS + i2) * C);

    const float4* cW4 = reinterpret_cast<const float4*>(cW);
    const float4* cB4 = reinterpret_cast<const float4*>(cB);

    float acc[64];
    #pragma unroll
    for (int m = 0; m < 16; ++m) {
        float4 bb = cB4[m];
        acc[4 * m + 0] = bb.x; acc[4 * m + 1] = bb.y;
        acc[4 * m + 2] = bb.z; acc[4 * m + 3] = bb.w;
    }

    for (int c4 = 0; c4 < 16; ++c4) {
        float4 a = __ldg(f0 + c4);
        float4 e = __ldg(f1 + c4);
        float4 g = __ldg(f2 + c4);
        float nf[4];
        nf[0] = __fmaf_rn(w0, a.x, __fmaf_rn(w1, e.x, w2 * g.x));
        nf[1] = __fmaf_rn(w0, a.y, __fmaf_rn(w1, e.y, w2 * g.y));
        nf[2] = __fmaf_rn(w0, a.z, __fmaf_rn(w1, e.z, w2 * g.z));
        nf[3] = __fmaf_rn(w0, a.w, __fmaf_rn(w1, e.w, w2 * g.w));

        const float4* wr = cW4 + (size_t)c4 * 4 * 16;
        #pragma unroll
        for (int kk = 0; kk < 4; ++kk) {
            float nfc = nf[kk];
            #pragma unroll
            for (int m = 0; m < 16; ++m) {
                float4 wv = wr[kk * 16 + m];
                acc[4 * m + 0] = __fmaf_rn(nfc, wv.x, acc[4 * m + 0]);
                acc[4 * m + 1] = __fmaf_rn(nfc, wv.y, acc[4 * m + 1]);
                acc[4 * m + 2] = __fmaf_rn(nfc, wv.z, acc[4 * m + 2]);
                acc[4 * m + 3] = __fmaf_rn(nfc, wv.w, acc[4 * m + 3]);
            }
        }
    }

    float4* o4 = reinterpret_cast<float4*>(out + (size_t)(b * NUP + q) * C);
    #pragma unroll
    for (int m = 0; m < 16; ++m) {
        float4 v;
        v.x = fmaxf(acc[4 * m + 0], 0.0f);
        v.y = fmaxf(acc[4 * m + 1], 0.0f);
        v.z = fmaxf(acc[4 * m + 2], 0.0f);
        v.w = fmaxf(acc[4 * m + 3], 0.0f);
        o4[m] = v;
    }
}

extern "C" void kernel_launch(void* const* d_in, const int* in_sizes, int n_in,
                              void* d_out, int out_size)
{
    const float* feature = (const float*)d_in[0];
    const float* pos     = (const float*)d_in[1];
    const float* pos_up  = (const float*)d_in[2];
    const float* W       = (const float*)d_in[3];
    const float* bias    = (const float*)d_in[4];
    float* out = (float*)d_out;

    cudaMemcpyToSymbolAsync(cW, W,    C * C * sizeof(float), 0, cudaMemcpyDeviceToDevice, 0);
    cudaMemcpyToSymbolAsync(cB, bias, C * sizeof(float),     0, cudaMemcpyDeviceToDevice, 0);

    cudaFuncSetAttribute(knn_slice_kernel, cudaFuncAttributeMaxDynamicSharedMemorySize, SMEM_A);

    dim3 gridA(NUP / QTILE, S, BATCH);      // (32, 4, 4) = 512 blocks
    knn_slice_kernel<<<gridA, TPB_A, SMEM_A>>>(pos, pos_up);

    dim3 gridB(NUP / TPB_B, BATCH);         // (64, 4) = 256 blocks
    epilogue_kernel<<<gridB, TPB_B>>>(feature, pos_up, out);
}

// round 5
// speedup vs baseline: 3.2276x; 1.0461x over previous
#include <cuda_runtime.h>
#include <math_constants.h>

static constexpr int NPTS  = 4096;
static constexpr int NUP   = 16384;
static constexpr int BATCH = 4;
static constexpr int C     = 64;

static constexpr int S      = 4;            // point slices
static constexpr int SLICE  = NPTS / S;     // 1024 points
static constexpr int TPB_A  = 128;
static constexpr int QA     = 2;            // queries per thread (phase A)
static constexpr int QTILE  = TPB_A * QA;   // 256 queries per block
static constexpr int TPB_B  = 128;          // 64 queries per block (2 thr/query)

__constant__ __align__(16) float cW[C * C];
__constant__ __align__(16) float cB[C];

// per-(slice, batch, query) top-3: values and indices (bitcast)
__device__ float4 g_scrV[S * BATCH * NUP];
__device__ float4 g_scrI[S * BATCH * NUP];

// ---- packed f32x2 helpers (Blackwell) ----
__device__ __forceinline__ unsigned long long pk2(float lo, float hi) {
    unsigned long long r;
    asm("mov.b64 %0, {%1, %2};" : "=l"(r) : "f"(lo), "f"(hi));
    return r;
}
__device__ __forceinline__ unsigned long long fma2(unsigned long long a,
                                                   unsigned long long b,
                                                   unsigned long long c) {
    unsigned long long d;
    asm("fma.rn.f32x2 %0, %1, %2, %3;" : "=l"(d) : "l"(a), "l"(b), "l"(c));
    return d;
}
__device__ __forceinline__ void unpk2(unsigned long long v, float& lo, float& hi) {
    asm("mov.b64 {%0, %1}, %2;" : "=f"(lo), "=f"(hi) : "l"(v));
}

// strict-< insert keeps earliest index on ties (jax.lax.top_k stability)
__device__ __forceinline__ void ins3(float v, int i,
                                     float& v0, float& v1, float& v2,
                                     int& i0, int& i1, int& i2) {
    if (v < v2) {
        if (v < v1) {
            v2 = v1; i2 = i1;
            if (v < v0) { v1 = v0; i1 = i0; v0 = v; i0 = i; }
            else        { v1 = v;  i1 = i; }
        } else { v2 = v; i2 = i; }
    }
}

// ================= Phase A: per-slice top-3 (points pair-packed in f32x2) ====
__global__ void __launch_bounds__(TPB_A, 8)
knn_slice_kernel(const float* __restrict__ pos,
                 const float* __restrict__ pos_up)
{
    __shared__ float4 spair[SLICE];   // [SLICE/2 pairs][2]: {x0,x1,y0,y1},{z0,z1,h0,h1}

    const int s   = blockIdx.y;
    const int b   = blockIdx.z;
    const int tid = threadIdx.x;

    // stage slice tile as point-pairs with half-norms
    {
        const float* pb = pos + ((size_t)b * NPTS + (size_t)s * SLICE) * 3;
        for (int p = tid; p < SLICE / 2; p += TPB_A) {
            const float* s6 = pb + 6 * p;
            float x0 = s6[0], y0 = s6[1], z0 = s6[2];
            float x1 = s6[3], y1 = s6[4], z1 = s6[5];
            spair[2 * p + 0] = make_float4(x0, x1, y0, y1);
            spair[2 * p + 1] = make_float4(z0, z1,
                                           0.5f * (x0 * x0 + y0 * y0 + z0 * z0),
                                           0.5f * (x1 * x1 + y1 * y1 + z1 * z1));
        }
    }
    __syncthreads();

    const int qbase = blockIdx.x * QTILE + tid;

    // hoisted duplicated (negated) query coords — loop-invariant
    unsigned long long nx[QA], ny[QA], nz[QA];
    #pragma unroll
    for (int k = 0; k < QA; ++k) {
        const int q = qbase + k * TPB_A;
        const float* pu = pos_up + (size_t)(b * NUP + q) * 3;
        float x = pu[0], y = pu[1], z = pu[2];
        nx[k] = pk2(-x, -x); ny[k] = pk2(-y, -y); nz[k] = pk2(-z, -z);
    }

    float v0[QA], v1[QA], v2[QA];
    int   i0[QA], i1[QA], i2[QA];
    #pragma unroll
    for (int k = 0; k < QA; ++k) {
        v0[k] = v1[k] = v2[k] = CUDART_INF_F;
        i0[k] = i1[k] = i2[k] = 0;
    }

    const int jbase = s * SLICE;

    #pragma unroll 2
    for (int p = 0; p < SLICE / 2; ++p) {
        float4 A  = spair[2 * p + 0];   // x0,x1,y0,y1
        float4 Bv = spair[2 * p + 1];   // z0,z1,h0,h1
        unsigned long long xs = pk2(A.x, A.y);
        unsigned long long ys = pk2(A.z, A.w);
        unsigned long long zs = pk2(Bv.x, Bv.y);
        unsigned long long hs = pk2(Bv.z, Bv.w);

        #pragma unroll
        for (int k = 0; k < QA; ++k) {
            unsigned long long sP = fma2(xs, nx[k], hs);
            sP = fma2(ys, ny[k], sP);
            sP = fma2(zs, nz[k], sP);
            float s0, s1;
            unpk2(sP, s0, s1);
            if (fminf(s0, s1) < v2[k]) {   // per-query tight gate, rare
                ins3(s0, jbase + 2 * p,     v0[k], v1[k], v2[k], i0[k], i1[k], i2[k]);
                ins3(s1, jbase + 2 * p + 1, v0[k], v1[k], v2[k], i0[k], i1[k], i2[k]);
            }
        }
    }

    #pragma unroll
    for (int k = 0; k < QA; ++k) {
        const int q = qbase + k * TPB_A;
        const size_t o = ((size_t)s * BATCH + b) * NUP + q;
        g_scrV[o] = make_float4(v0[k], v1[k], v2[k], 0.0f);
        g_scrI[o] = make_float4(__int_as_float(i0[k]), __int_as_float(i1[k]),
                                __int_as_float(i2[k]), 0.0f);
    }
}

// ====== Phase B: merge + interp + GEMM, 2 threads per query (d-halves) ======
__global__ void __launch_bounds__(TPB_B, 6)
epilogue_kernel(const float* __restrict__ feature,
                const float* __restrict__ pos_up,
                float* __restrict__ out)
{
    const int b    = blockIdx.y;
    const int half = threadIdx.x & 1;                          // d-half: 0 or 1
    const int q    = blockIdx.x * (TPB_B / 2) + (threadIdx.x >> 1);

    // merge S slice-top-3s (ascending slice order, strict < => global stability)
    float v0 = CUDART_INF_F, v1 = CUDART_INF_F, v2 = CUDART_INF_F;
    int   i0 = 0, i1 = 0, i2 = 0;
    #pragma unroll
    for (int s = 0; s < S; ++s) {
        const size_t o = ((size_t)s * BATCH + b) * NUP + q;
        float4 vv = g_scrV[o];
        float4 ii = g_scrI[o];
        ins3(vv.x, __float_as_int(ii.x), v0, v1, v2, i0, i1, i2);
        ins3(vv.y, __float_as_int(ii.y), v0, v1, v2, i0, i1, i2);
        ins3(vv.z, __float_as_int(ii.z), v0, v1, v2, i0, i1, i2);
    }

    const float* pu = pos_up + (size_t)(b * NUP + q) * 3;
    const float pux = pu[0], puy = pu[1], puz = pu[2];
    const float nu  = pux * pux + puy * puy + puz * puz;

    float w0 = 1.0f / (__fmaf_rn(2.0f, v0, nu) + 1e-6f);
    float w1 = 1.0f / (__fmaf_rn(2.0f, v1, nu) + 1e-6f);
    float w2 = 1.0f / (__fmaf_rn(2.0f, v2, nu) + 1e-6f);
    float inv = 1.0f / (w0 + w1 + w2);
    w0 *= inv; w1 *= inv; w2 *= inv;

    const float4* f0 = reinterpret_cast<const float4*>(feature + (size_t)(b * NPTS + i0) * C);
    const float4* f1 = reinterpret_cast<const float4*>(feature + (size_t)(b * NPTS + i1) * C);
    const float4* f2 = reinterpret_cast<const float4*>(feature + (size_t)(b * NPTS + i2) * C);

    const float4* cW4 = reinterpret_cast<const float4*>(cW);
    const float4* cB4 = reinterpret_cast<const float4*>(cB);

    float acc[32];
    #pragma unroll
    for (int m = 0; m < 8; ++m) {
        float4 bb = cB4[half * 8 + m];
        acc[4 * m + 0] = bb.x; acc[4 * m + 1] = bb.y;
        acc[4 * m + 2] = bb.z; acc[4 * m + 3] = bb.w;
    }

    #pragma unroll 2
    for (int c4 = 0; c4 < 16; ++c4) {
        float4 a = __ldg(f0 + c4);
        float4 e = __ldg(f1 + c4);
        float4 g = __ldg(f2 + c4);
        float nf[4];
        nf[0] = __fmaf_rn(w0, a.x, __fmaf_rn(w1, e.x, w2 * g.x));
        nf[1] = __fmaf_rn(w0, a.y, __fmaf_rn(w1, e.y, w2 * g.y));
        nf[2] = __fmaf_rn(w0, a.z, __fmaf_rn(w1, e.z, w2 * g.z));
        nf[3] = __fmaf_rn(w0, a.w, __fmaf_rn(w1, e.w, w2 * g.w));

        #pragma unroll
        for (int kk = 0; kk < 4; ++kk) {
            float nfc = nf[kk];
            const float4* wr = cW4 + (size_t)(4 * c4 + kk) * 16 + half * 8;
            #pragma unroll
            for (int m = 0; m < 8; ++m) {
                float4 wv = wr[m];
                acc[4 * m + 0] = __fmaf_rn(nfc, wv.x, acc[4 * m + 0]);
                acc[4 * m + 1] = __fmaf_rn(nfc, wv.y, acc[4 * m + 1]);
                acc[4 * m + 2] = __fmaf_rn(nfc, wv.z, acc[4 * m + 2]);
                acc[4 * m + 3] = __fmaf_rn(nfc, wv.w, acc[4 * m + 3]);
            }
        }
    }

    float4* o4 = reinterpret_cast<float4*>(out + (size_t)(b * NUP + q) * C + half * 32);
    #pragma unroll
    for (int m = 0; m < 8; ++m) {
        float4 v;
        v.x = fmaxf(acc[4 * m + 0], 0.0f);
        v.y = fmaxf(acc[4 * m + 1], 0.0f);
        v.z = fmaxf(acc[4 * m + 2], 0.0f);
        v.w = fmaxf(acc[4 * m + 3], 0.0f);
        o4[m] = v;
    }
}

extern "C" void kernel_launch(void* const* d_in, const int* in_sizes, int n_in,
                              void* d_out, int out_size)
{
    const float* feature = (const float*)d_in[0];
    const float* pos     = (const float*)d_in[1];
    const float* pos_up  = (const float*)d_in[2];
    const float* W       = (const float*)d_in[3];
    const float* bias    = (const float*)d_in[4];
    float* out = (float*)d_out;

    cudaMemcpyToSymbolAsync(cW, W,    C * C * sizeof(float), 0, cudaMemcpyDeviceToDevice, 0);
    cudaMemcpyToSymbolAsync(cB, bias, C * sizeof(float),     0, cudaMemcpyDeviceToDevice, 0);

    dim3 gridA(NUP / QTILE, S, BATCH);           // (64, 4, 4) = 1024 blocks
    knn_slice_kernel<<<gridA, TPB_A>>>(pos, pos_up);

    dim3 gridB(NUP / (TPB_B / 2), BATCH);        // (256, 4) = 1024 blocks
    epilogue_kernel<<<gridB, TPB_B>>>(feature, pos_up, out);
}

// round 6
// speedup vs baseline: 3.5745x; 1.1075x over previous
#include <cuda_runtime.h>
#include <math_constants.h>

static constexpr int NPTS  = 4096;
static constexpr int NUP   = 16384;
static constexpr int BATCH = 4;
static constexpr int C     = 64;

static constexpr int S      = 8;            // point slices
static constexpr int SLICE  = NPTS / S;     // 512 points
static constexpr int TPB_A  = 128;
static constexpr int QA     = 2;            // queries per thread (phase A)
static constexpr int QTILE  = TPB_A * QA;   // 256 queries per block
static constexpr int TPB_B  = 128;          // 4 warps: 2 query-groups x 2 d-halves

__constant__ __align__(16) float cW[C * C];
__constant__ __align__(16) float cB[C];

// per-(slice, batch, query) top-3: values and indices (bitcast)
__device__ float4 g_scrV[S * BATCH * NUP];
__device__ float4 g_scrI[S * BATCH * NUP];

// ---- packed f32x2 helpers (Blackwell) ----
__device__ __forceinline__ unsigned long long pk2(float lo, float hi) {
    unsigned long long r;
    asm("mov.b64 %0, {%1, %2};" : "=l"(r) : "f"(lo), "f"(hi));
    return r;
}
__device__ __forceinline__ unsigned long long fma2(unsigned long long a,
                                                   unsigned long long b,
                                                   unsigned long long c) {
    unsigned long long d;
    asm("fma.rn.f32x2 %0, %1, %2, %3;" : "=l"(d) : "l"(a), "l"(b), "l"(c));
    return d;
}
__device__ __forceinline__ void unpk2(unsigned long long v, float& lo, float& hi) {
    asm("mov.b64 {%0, %1}, %2;" : "=f"(lo), "=f"(hi) : "l"(v));
}

// strict-< insert keeps earliest index on ties (jax.lax.top_k stability)
__device__ __forceinline__ void ins3(float v, int i,
                                     float& v0, float& v1, float& v2,
                                     int& i0, int& i1, int& i2) {
    if (v < v2) {
        if (v < v1) {
            v2 = v1; i2 = i1;
            if (v < v0) { v1 = v0; i1 = i0; v0 = v; i0 = i; }
            else        { v1 = v;  i1 = i; }
        } else { v2 = v; i2 = i; }
    }
}

// ============ Phase A: per-slice top-3, points pair-packed as u64 lanes ======
__global__ void __launch_bounds__(TPB_A, 8)
knn_slice_kernel(const float* __restrict__ pos,
                 const float* __restrict__ pos_up)
{
    // pair p: [2p] = {(x0,x1),(y0,y1)}, [2p+1] = {(z0,z1),(h0,h1)}
    __shared__ ulonglong2 spair[SLICE];

    const int s   = blockIdx.y;
    const int b   = blockIdx.z;
    const int tid = threadIdx.x;

    {
        const float* pb = pos + ((size_t)b * NPTS + (size_t)s * SLICE) * 3;
        for (int p = tid; p < SLICE / 2; p += TPB_A) {
            const float* s6 = pb + 6 * p;
            float x0 = s6[0], y0 = s6[1], z0 = s6[2];
            float x1 = s6[3], y1 = s6[4], z1 = s6[5];
            ulonglong2 A, B;
            A.x = pk2(x0, x1);
            A.y = pk2(y0, y1);
            B.x = pk2(z0, z1);
            B.y = pk2(0.5f * (x0 * x0 + y0 * y0 + z0 * z0),
                      0.5f * (x1 * x1 + y1 * y1 + z1 * z1));
            spair[2 * p + 0] = A;
            spair[2 * p + 1] = B;
        }
    }
    __syncthreads();

    const int qbase = blockIdx.x * QTILE + tid;

    unsigned long long nx[QA], ny[QA], nz[QA];
    #pragma unroll
    for (int k = 0; k < QA; ++k) {
        const int q = qbase + k * TPB_A;
        const float* pu = pos_up + (size_t)(b * NUP + q) * 3;
        float x = pu[0], y = pu[1], z = pu[2];
        nx[k] = pk2(-x, -x); ny[k] = pk2(-y, -y); nz[k] = pk2(-z, -z);
    }

    float v0[QA], v1[QA], v2[QA];
    int   i0[QA], i1[QA], i2[QA];
    #pragma unroll
    for (int k = 0; k < QA; ++k) {
        v0[k] = v1[k] = v2[k] = CUDART_INF_F;
        i0[k] = i1[k] = i2[k] = 0;
    }

    const int jbase = s * SLICE;

    #pragma unroll 4
    for (int p = 0; p < SLICE / 2; ++p) {
        ulonglong2 A  = spair[2 * p + 0];   // xs, ys (packed point-pairs)
        ulonglong2 Bv = spair[2 * p + 1];   // zs, hs

        #pragma unroll
        for (int k = 0; k < QA; ++k) {
            unsigned long long sP = fma2(A.x, nx[k], Bv.y);
            sP = fma2(A.y, ny[k], sP);
            sP = fma2(Bv.x, nz[k], sP);
            float s0, s1;
            unpk2(sP, s0, s1);
            if (fminf(s0, s1) < v2[k]) {     // per-query tight gate, rare
                ins3(s0, jbase + 2 * p,     v0[k], v1[k], v2[k], i0[k], i1[k], i2[k]);
                ins3(s1, jbase + 2 * p + 1, v0[k], v1[k], v2[k], i0[k], i1[k], i2[k]);
            }
        }
    }

    #pragma unroll
    for (int k = 0; k < QA; ++k) {
        const int q = qbase + k * TPB_A;
        const size_t o = ((size_t)s * BATCH + b) * NUP + q;
        g_scrV[o] = make_float4(v0[k], v1[k], v2[k], 0.0f);
        g_scrI[o] = make_float4(__int_as_float(i0[k]), __int_as_float(i1[k]),
                                __int_as_float(i2[k]), 0.0f);
    }
}

// ====== Phase B: merge + interp + GEMM; d-half split is WARP-uniform ========
__global__ void __launch_bounds__(TPB_B, 6)
epilogue_kernel(const float* __restrict__ feature,
                const float* __restrict__ pos_up,
                float* __restrict__ out)
{
    const int b    = blockIdx.y;
    const int wid  = threadIdx.x >> 5;
    const int lane = threadIdx.x & 31;
    const int half = wid & 1;                       // warp-uniform d-half
    const int q    = blockIdx.x * 64 + (wid >> 1) * 32 + lane;

    // merge S slice-top-3s (ascending slice order, strict < => global stability)
    float v0 = CUDART_INF_F, v1 = CUDART_INF_F, v2 = CUDART_INF_F;
    int   i0 = 0, i1 = 0, i2 = 0;
    #pragma unroll
    for (int s = 0; s < S; ++s) {
        const size_t o = ((size_t)s * BATCH + b) * NUP + q;
        float4 vv = g_scrV[o];
        float4 ii = g_scrI[o];
        ins3(vv.x, __float_as_int(ii.x), v0, v1, v2, i0, i1, i2);
        ins3(vv.y, __float_as_int(ii.y), v0, v1, v2, i0, i1, i2);
        ins3(vv.z, __float_as_int(ii.z), v0, v1, v2, i0, i1, i2);
    }

    const float* pu = pos_up + (size_t)(b * NUP + q) * 3;
    const float pux = pu[0], puy = pu[1], puz = pu[2];
    const float nu  = pux * pux + puy * puy + puz * puz;

    float w0 = 1.0f / (__fmaf_rn(2.0f, v0, nu) + 1e-6f);
    float w1 = 1.0f / (__fmaf_rn(2.0f, v1, nu) + 1e-6f);
    float w2 = 1.0f / (__fmaf_rn(2.0f, v2, nu) + 1e-6f);
    float inv = 1.0f / (w0 + w1 + w2);
    w0 *= inv; w1 *= inv; w2 *= inv;

    const float4* f0 = reinterpret_cast<const float4*>(feature + (size_t)(b * NPTS + i0) * C);
    const float4* f1 = reinterpret_cast<const float4*>(feature + (size_t)(b * NPTS + i1) * C);
    const float4* f2 = reinterpret_cast<const float4*>(feature + (size_t)(b * NPTS + i2) * C);

    const float4* cW4 = reinterpret_cast<const float4*>(cW);
    const float4* cB4 = reinterpret_cast<const float4*>(cB);

    float acc[32];
    #pragma unroll
    for (int m = 0; m < 8; ++m) {
        float4 bb = cB4[half * 8 + m];
        acc[4 * m + 0] = bb.x; acc[4 * m + 1] = bb.y;
        acc[4 * m + 2] = bb.z; acc[4 * m + 3] = bb.w;
    }

    #pragma unroll 2
    for (int c4 = 0; c4 < 16; ++c4) {
        float4 a = __ldg(f0 + c4);
        float4 e = __ldg(f1 + c4);
        float4 g = __ldg(f2 + c4);
        float nf[4];
        nf[0] = __fmaf_rn(w0, a.x, __fmaf_rn(w1, e.x, w2 * g.x));
        nf[1] = __fmaf_rn(w0, a.y, __fmaf_rn(w1, e.y, w2 * g.y));
        nf[2] = __fmaf_rn(w0, a.z, __fmaf_rn(w1, e.z, w2 * g.z));
        nf[3] = __fmaf_rn(w0, a.w, __fmaf_rn(w1, e.w, w2 * g.w));

        #pragma unroll
        for (int kk = 0; kk < 4; ++kk) {
            float nfc = nf[kk];
            const float4* wr = cW4 + (size_t)(4 * c4 + kk) * 16 + half * 8; // warp-uniform
            #pragma unroll
            for (int m = 0; m < 8; ++m) {
                float4 wv = wr[m];
                acc[4 * m + 0] = __fmaf_rn(nfc, wv.x, acc[4 * m + 0]);
                acc[4 * m + 1] = __fmaf_rn(nfc, wv.y, acc[4 * m + 1]);
                acc[4 * m + 2] = __fmaf_rn(nfc, wv.z, acc[4 * m + 2]);
                acc[4 * m + 3] = __fmaf_rn(nfc, wv.w, acc[4 * m + 3]);
            }
        }
    }

    float4* o4 = reinterpret_cast<float4*>(out + (size_t)(b * NUP + q) * C + half * 32);
    #pragma unroll
    for (int m = 0; m < 8; ++m) {
        float4 v;
        v.x = fmaxf(acc[4 * m + 0], 0.0f);
        v.y = fmaxf(acc[4 * m + 1], 0.0f);
        v.z = fmaxf(acc[4 * m + 2], 0.0f);
        v.w = fmaxf(acc[4 * m + 3], 0.0f);
        o4[m] = v;
    }
}

extern "C" void kernel_launch(void* const* d_in, const int* in_sizes, int n_in,
                              void* d_out, int out_size)
{
    const float* feature = (const float*)d_in[0];
    const float* pos     = (const float*)d_in[1];
    const float* pos_up  = (const float*)d_in[2];
    const float* W       = (const float*)d_in[3];
    const float* bias    = (const float*)d_in[4];
    float* out = (float*)d_out;

    cudaMemcpyToSymbolAsync(cW, W,    C * C * sizeof(float), 0, cudaMemcpyDeviceToDevice, 0);
    cudaMemcpyToSymbolAsync(cB, bias, C * sizeof(float),     0, cudaMemcpyDeviceToDevice, 0);

    dim3 gridA(NUP / QTILE, S, BATCH);      // (64, 8, 4) = 2048 blocks
    knn_slice_kernel<<<gridA, TPB_A>>>(pos, pos_up);

    dim3 gridB(NUP / 64, BATCH);            // (256, 4) = 1024 blocks
    epilogue_kernel<<<gridB, TPB_B>>>(feature, pos_up, out);
}

// round 7
// speedup vs baseline: 4.2705x; 1.1947x over previous
#include <cuda_runtime.h>
#include <math_constants.h>

static constexpr int NPTS  = 4096;
static constexpr int NUP   = 16384;
static constexpr int BATCH = 4;
static constexpr int C     = 64;

static constexpr int S      = 4;            // point slices (measured best)
static constexpr int SLICE  = NPTS / S;     // 1024 points
static constexpr int TPB_A  = 128;
static constexpr int QA     = 2;            // queries per thread (phase A)
static constexpr int QTILE  = TPB_A * QA;   // 256 queries per block
static constexpr int TPB_B  = 256;

__constant__ __align__(16) float cW[C * C];
__constant__ __align__(16) float cB[C];

// per-(slice, batch, query) top-3: values and indices (bitcast)
__device__ float4 g_scrV[S * BATCH * NUP];
__device__ float4 g_scrI[S * BATCH * NUP];

// ---- packed f32x2 helpers (Blackwell) ----
__device__ __forceinline__ unsigned long long pk2(float lo, float hi) {
    unsigned long long r;
    asm("mov.b64 %0, {%1, %2};" : "=l"(r) : "f"(lo), "f"(hi));
    return r;
}
__device__ __forceinline__ unsigned long long fma2(unsigned long long a,
                                                   unsigned long long b,
                                                   unsigned long long c) {
    unsigned long long d;
    asm("fma.rn.f32x2 %0, %1, %2, %3;" : "=l"(d) : "l"(a), "l"(b), "l"(c));
    return d;
}
__device__ __forceinline__ void unpk2(unsigned long long v, float& lo, float& hi) {
    asm("mov.b64 {%0, %1}, %2;" : "=f"(lo), "=f"(hi) : "l"(v));
}

// strict-< insert keeps earliest index on ties (jax.lax.top_k stability)
__device__ __forceinline__ void ins3(float v, int i,
                                     float& v0, float& v1, float& v2,
                                     int& i0, int& i1, int& i2) {
    if (v < v2) {
        if (v < v1) {
            v2 = v1; i2 = i1;
            if (v < v0) { v1 = v0; i1 = i0; v0 = v; i0 = i; }
            else        { v1 = v;  i1 = i; }
        } else { v2 = v; i2 = i; }
    }
}

// ============ Phase A: per-slice top-3, points pair-packed as u64 lanes ======
__global__ void __launch_bounds__(TPB_A, 8)
knn_slice_kernel(const float* __restrict__ pos,
                 const float* __restrict__ pos_up)
{
    // pair p: [2p] = {(x0,x1),(y0,y1)}, [2p+1] = {(z0,z1),(h0,h1)}
    __shared__ ulonglong2 spair[SLICE];

    const int s   = blockIdx.y;
    const int b   = blockIdx.z;
    const int tid = threadIdx.x;

    {
        const float* pb = pos + ((size_t)b * NPTS + (size_t)s * SLICE) * 3;
        for (int p = tid; p < SLICE / 2; p += TPB_A) {
            const float* s6 = pb + 6 * p;
            float x0 = s6[0], y0 = s6[1], z0 = s6[2];
            float x1 = s6[3], y1 = s6[4], z1 = s6[5];
            ulonglong2 A, B;
            A.x = pk2(x0, x1);
            A.y = pk2(y0, y1);
            B.x = pk2(z0, z1);
            B.y = pk2(0.5f * (x0 * x0 + y0 * y0 + z0 * z0),
                      0.5f * (x1 * x1 + y1 * y1 + z1 * z1));
            spair[2 * p + 0] = A;
            spair[2 * p + 1] = B;
        }
    }
    __syncthreads();

    const int qbase = blockIdx.x * QTILE + tid;

    unsigned long long nx[QA], ny[QA], nz[QA];
    #pragma unroll
    for (int k = 0; k < QA; ++k) {
        const int q = qbase + k * TPB_A;
        const float* pu = pos_up + (size_t)(b * NUP + q) * 3;
        float x = pu[0], y = pu[1], z = pu[2];
        nx[k] = pk2(-x, -x); ny[k] = pk2(-y, -y); nz[k] = pk2(-z, -z);
    }

    float v0[QA], v1[QA], v2[QA];
    int   i0[QA], i1[QA], i2[QA];
    #pragma unroll
    for (int k = 0; k < QA; ++k) {
        v0[k] = v1[k] = v2[k] = CUDART_INF_F;
        i0[k] = i1[k] = i2[k] = 0;
    }

    const int jbase = s * SLICE;

    #pragma unroll 4
    for (int p = 0; p < SLICE / 2; ++p) {
        ulonglong2 A  = spair[2 * p + 0];   // xs, ys (packed point-pairs)
        ulonglong2 Bv = spair[2 * p + 1];   // zs, hs

        #pragma unroll
        for (int k = 0; k < QA; ++k) {
            unsigned long long sP = fma2(A.x, nx[k], Bv.y);
            sP = fma2(A.y, ny[k], sP);
            sP = fma2(Bv.x, nz[k], sP);
            float s0, s1;
            unpk2(sP, s0, s1);
            if (fminf(s0, s1) < v2[k]) {     // per-query gate
                ins3(s0, jbase + 2 * p,     v0[k], v1[k], v2[k], i0[k], i1[k], i2[k]);
                ins3(s1, jbase + 2 * p + 1, v0[k], v1[k], v2[k], i0[k], i1[k], i2[k]);
            }
        }
    }

    #pragma unroll
    for (int k = 0; k < QA; ++k) {
        const int q = qbase + k * TPB_A;
        const size_t o = ((size_t)s * BATCH + b) * NUP + q;
        g_scrV[o] = make_float4(v0[k], v1[k], v2[k], 0.0f);
        g_scrI[o] = make_float4(__int_as_float(i0[k]), __int_as_float(i1[k]),
                                __int_as_float(i2[k]), 0.0f);
    }
}

// ====== Phase B: merge + interp + f32x2 GEMM, 1 thread per query ============
__global__ void __launch_bounds__(TPB_B, 2)
epilogue_kernel(const float* __restrict__ feature,
                const float* __restrict__ pos_up,
                float* __restrict__ out)
{
    const int b = blockIdx.y;
    const int q = blockIdx.x * TPB_B + threadIdx.x;

    // merge S slice-top-3s (ascending slice order, strict < => global stability)
    float v0 = CUDART_INF_F, v1 = CUDART_INF_F, v2 = CUDART_INF_F;
    int   i0 = 0, i1 = 0, i2 = 0;
    #pragma unroll
    for (int s = 0; s < S; ++s) {
        const size_t o = ((size_t)s * BATCH + b) * NUP + q;
        float4 vv = g_scrV[o];
        float4 ii = g_scrI[o];
        ins3(vv.x, __float_as_int(ii.x), v0, v1, v2, i0, i1, i2);
        ins3(vv.y, __float_as_int(ii.y), v0, v1, v2, i0, i1, i2);
        ins3(vv.z, __float_as_int(ii.z), v0, v1, v2, i0, i1, i2);
    }

    const float* pu = pos_up + (size_t)(b * NUP + q) * 3;
    const float pux = pu[0], puy = pu[1], puz = pu[2];
    const float nu  = pux * pux + puy * puy + puz * puz;

    float w0 = 1.0f / (__fmaf_rn(2.0f, v0, nu) + 1e-6f);
    float w1 = 1.0f / (__fmaf_rn(2.0f, v1, nu) + 1e-6f);
    float w2 = 1.0f / (__fmaf_rn(2.0f, v2, nu) + 1e-6f);
    float inv = 1.0f / (w0 + w1 + w2);
    w0 *= inv; w1 *= inv; w2 *= inv;

    const float4* f0 = reinterpret_cast<const float4*>(feature + (size_t)(b * NPTS + i0) * C);
    const float4* f1 = reinterpret_cast<const float4*>(feature + (size_t)(b * NPTS + i1) * C);
    const float4* f2 = reinterpret_cast<const float4*>(feature + (size_t)(b * NPTS + i2) * C);

    // W and bias viewed as packed f32x2 (d-pairs); addressing is warp-uniform
    const unsigned long long* cW2 = reinterpret_cast<const unsigned long long*>(cW);
    const unsigned long long* cB2 = reinterpret_cast<const unsigned long long*>(cB);

    unsigned long long acc2[32];     // outputs as 32 packed d-pairs
    #pragma unroll
    for (int m = 0; m < 32; ++m) acc2[m] = cB2[m];

    #pragma unroll 4
    for (int c4 = 0; c4 < 16; ++c4) {
        float4 a = __ldg(f0 + c4);
        float4 e = __ldg(f1 + c4);
        float4 g = __ldg(f2 + c4);
        float nf[4];
        nf[0] = __fmaf_rn(w0, a.x, __fmaf_rn(w1, e.x, w2 * g.x));
        nf[1] = __fmaf_rn(w0, a.y, __fmaf_rn(w1, e.y, w2 * g.y));
        nf[2] = __fmaf_rn(w0, a.z, __fmaf_rn(w1, e.z, w2 * g.z));
        nf[3] = __fmaf_rn(w0, a.w, __fmaf_rn(w1, e.w, w2 * g.w));

        #pragma unroll
        for (int kk = 0; kk < 4; ++kk) {
            const unsigned long long nf2 = pk2(nf[kk], nf[kk]);  // broadcast pack
            const unsigned long long* wr = cW2 + (size_t)(4 * c4 + kk) * 32;
            #pragma unroll
            for (int m = 0; m < 32; ++m)
                acc2[m] = fma2(nf2, wr[m], acc2[m]);             // 2 outputs / instr
        }
    }

    // ReLU on unpacked halves + vectorized store
    float4* o4 = reinterpret_cast<float4*>(out + (size_t)(b * NUP + q) * C);
    #pragma unroll
    for (int m = 0; m < 16; ++m) {
        float x0, x1, x2, x3;
        unpk2(acc2[2 * m + 0], x0, x1);
        unpk2(acc2[2 * m + 1], x2, x3);
        float4 v;
        v.x = fmaxf(x0, 0.0f);
        v.y = fmaxf(x1, 0.0f);
        v.z = fmaxf(x2, 0.0f);
        v.w = fmaxf(x3, 0.0f);
        o4[m] = v;
    }
}

extern "C" void kernel_launch(void* const* d_in, const int* in_sizes, int n_in,
                              void* d_out, int out_size)
{
    const float* feature = (const float*)d_in[0];
    const float* pos     = (const float*)d_in[1];
    const float* pos_up  = (const float*)d_in[2];
    const float* W       = (const float*)d_in[3];
    const float* bias    = (const float*)d_in[4];
    float* out = (float*)d_out;

    cudaMemcpyToSymbolAsync(cW, W,    C * C * sizeof(float), 0, cudaMemcpyDeviceToDevice, 0);
    cudaMemcpyToSymbolAsync(cB, bias, C * sizeof(float),     0, cudaMemcpyDeviceToDevice, 0);

    dim3 gridA(NUP / QTILE, S, BATCH);      // (64, 4, 4) = 1024 blocks
    knn_slice_kernel<<<gridA, TPB_A>>>(pos, pos_up);

    dim3 gridB(NUP / TPB_B, BATCH);         // (64, 4) = 256 blocks
    epilogue_kernel<<<gridB, TPB_B>>>(feature, pos_up, out);
}